// round 9
// baseline (speedup 1.0000x reference)
#include <cuda_runtime.h>

#define NN   65536      // nodes
#define EE   1048576    // edges (NN*16)
#define CIN  128
#define COUT 64

#define GRID 592        // 4 blocks/SM, one wave
#define NWARPS (GRID * 8)       // 4736
#define NTHREADS (GRID * 256)   // 151552

// Scratch (no allocations allowed -> __device__ globals)
__device__ float g_T[NN];      // T[i] = x[i] . w_sum
__device__ int   g_start[NN];  // first edge index of node i's run (rows sorted)
__device__ int   g_end[NN];    // one-past-last edge index of node i's run
__device__ float g_sP[NN];     // s values at permuted positions 0..NN-1 (only ones used)
__device__ int   g_is64;       // 1 if edge_index stored as int64
__device__ int   g_i0;         // rotation offset from int32-overflow argsort (0 if int64)

// Pairwise merge: one shuffle merges two reduction trees.
__device__ __forceinline__ float merge_red(float a, float b, int dist, int lane) {
    bool hi = (lane & dist) != 0;
    float x = __shfl_xor_sync(0xffffffffu, hi ? a : b, dist);
    return (hi ? b : a) + x;
}

// K1: every warp does (a) its grid-strided share of T[i]=x[i].wsum (batch-8, MLP=8),
//     then (b) its grid-strided share of the run-boundary pass. No block sync between
//     phases -> warps self-balance; total work identical across blocks -> no SM tail.
__global__ __launch_bounds__(256, 4) void k_main(const float* __restrict__ x,
                                                 const float* __restrict__ w,
                                                 const int* __restrict__ e32) {
    __shared__ __align__(16) float s_ws[CIN];
    __shared__ int s_is64;
    int t = threadIdx.x, lane = t & 31, wrp = t >> 5;

    // dtype detect: int64 => all odd int32 words are zero high-words
    if (wrp == 0) {
        int v = (lane < 16) ? e32[2 * lane + 1] : 0;
        unsigned b = __ballot_sync(0xffffffffu, v != 0);
        if (lane == 0) s_is64 = (b == 0) ? 1 : 0;
    }
    // wsum[c] = sum_o W[c][o]; coalesced warp reductions (w is L2-hot across blocks)
    for (int c = wrp; c < CIN; c += 8) {
        float a = w[c * COUT + lane] + w[c * COUT + 32 + lane];
        #pragma unroll
        for (int o = 16; o; o >>= 1) a += __shfl_xor_sync(0xffffffffu, a, o);
        if (lane == 0) s_ws[c] = a;
    }
    __syncthreads();
    int is64 = s_is64;

    // block 0, warp 7: 32-ary search for first row >= 32768 (int32-overflow rotation)
    if (blockIdx.x == 0 && wrp == 7) {
        int i0 = 0;
        if (!is64) {
            int lo = 0, hi = EE;
            while (hi - lo > 64) {
                long long len = hi - lo;
                int q = lo + (int)((len * (lane + 1)) / 33);
                int val = e32[(size_t)q * 2];
                unsigned b = __ballot_sync(0xffffffffu, val >= 32768);
                if (b == 0) {
                    lo = lo + (int)((len * 32) / 33);
                } else {
                    int k = __ffs(b) - 1;
                    int nhi = lo + (int)((len * (k + 1)) / 33);
                    int nlo = (k == 0) ? lo : (lo + (int)((len * (long long)k) / 33));
                    lo = nlo; hi = nhi;
                }
            }
            int p1 = lo + lane, p2 = lo + 32 + lane;
            int c1 = (p1 < hi && e32[(size_t)p1 * 2] < 32768) ? 1 : 0;
            int c2 = (p2 < hi && e32[(size_t)p2 * 2] < 32768) ? 1 : 0;
            unsigned b1 = __ballot_sync(0xffffffffu, c1);
            unsigned b2 = __ballot_sync(0xffffffffu, c2);
            i0 = lo + __popc(b1) + __popc(b2);
        }
        if (lane == 0) { g_is64 = is64; g_i0 = i0; }
    }

    // ---- Phase A: T. 8 consecutive nodes per warp-iter (8 LDG.128 in flight). ----
    {
        float4 wv = ((const float4*)s_ws)[lane];
        int wid = blockIdx.x * 8 + wrp;
        for (int base = wid * 8; base < NN; base += NWARPS * 8) {
            float s[8];
            #pragma unroll
            for (int i = 0; i < 8; i++) {
                float4 xv = ((const float4*)(x + (size_t)(base + i) * CIN))[lane];
                s[i] = xv.x * wv.x + xv.y * wv.y + xv.z * wv.z + xv.w * wv.w;
            }
            float m0 = merge_red(s[0], s[1], 16, lane);
            float m1 = merge_red(s[2], s[3], 16, lane);
            float m2 = merge_red(s[4], s[5], 16, lane);
            float m3 = merge_red(s[6], s[7], 16, lane);
            float n0 = merge_red(m0, m1, 8, lane);
            float n1 = merge_red(m2, m3, 8, lane);
            float p  = merge_red(n0, n1, 4, lane);
            p += __shfl_xor_sync(0xffffffffu, p, 2);
            p += __shfl_xor_sync(0xffffffffu, p, 1);
            if ((lane & 3) == 0) {
                int off = ((lane >> 4) & 1) + ((lane >> 3) & 1) * 2 + ((lane >> 2) & 1) * 4;
                g_T[base + off] = p;
            }
        }
    }

    // ---- Phase B: run-boundary stores over sorted rows (batch-4 int4, MLP ~8). ----
    {
        int gt = blockIdx.x * 256 + t;
        const int4* p4 = (const int4*)e32;
        if (!is64) {
            const int U = EE / 2;                        // 524288 int4 units
            for (int g0 = gt; g0 < U; g0 += 4 * NTHREADS) {
                int4 v[4]; int rn[4]; int gi[4]; int nv = 0;
                #pragma unroll
                for (int i = 0; i < 4; i++) {
                    int g = g0 + i * NTHREADS;
                    if (g < U) {
                        gi[nv] = g;
                        v[nv] = p4[g];
                        size_t pk = (g < U - 1) ? (size_t)(2 * g + 2) * 2 : 0;
                        rn[nv] = __ldg(&e32[pk]);
                        nv++;
                    }
                }
                #pragma unroll
                for (int i = 0; i < 4; i++) {
                    if (i < nv) {
                        int g = gi[i];
                        int4 e = v[i];                   // edges 2g:(x,y) 2g+1:(z,w)
                        if (g == 0) g_start[e.x] = 0;
                        if (e.x != e.z) { g_end[e.x] = 2 * g + 1; g_start[e.z] = 2 * g + 1; }
                        if (g == U - 1) {
                            g_end[e.z] = EE;
                        } else if (e.z != rn[i]) {
                            g_end[e.z] = 2 * g + 2; g_start[rn[i]] = 2 * g + 2;
                        }
                    }
                }
            }
        } else {
            const int U = EE;                            // one edge per int4
            for (int g0 = gt; g0 < U; g0 += 4 * NTHREADS) {
                int4 v[4]; int rn[4]; int gi[4]; int nv = 0;
                #pragma unroll
                for (int i = 0; i < 4; i++) {
                    int g = g0 + i * NTHREADS;
                    if (g < U) {
                        gi[nv] = g;
                        v[nv] = p4[g];
                        size_t pk = (g < U - 1) ? (size_t)(g + 1) * 4 : 0;
                        rn[nv] = __ldg(&e32[pk]);
                        nv++;
                    }
                }
                #pragma unroll
                for (int i = 0; i < 4; i++) {
                    if (i < nv) {
                        int g = gi[i];
                        int4 e = v[i];                   // edge g: row=x, col=z
                        if (g == 0) g_start[e.x] = 0;
                        if (g == U - 1) {
                            g_end[e.x] = EE;
                        } else if (e.x != rn[i]) {
                            g_end[e.x] = g + 1; g_start[rn[i]] = g + 1;
                        }
                    }
                }
            }
        }
    }
}

// K2: sP[j] = 2*T[r]/(cnt[r]+1+1e-16)/ed[m], only for the NN positions ever gathered.
__global__ __launch_bounds__(256) void k_sP(const int* __restrict__ e32,
                                            const float* __restrict__ ed) {
    int j = blockIdx.x * 256 + threadIdx.x;              // j < NN
    int m = j + g_i0; if (m >= EE) m -= EE;
    int stride = g_is64 ? 4 : 2;
    int r = __ldg(&e32[(size_t)m * stride]);
    int cnt = g_end[r] - g_start[r];                     // out-degree (excl. self loop)
    float coef = 2.0f * g_T[r] / ((float)(cnt + 1) + 1e-16f);
    g_sP[j] = coef / ed[m];
}

// K3: out[j] = sP[row[rot(j)]] - sP[col[rot(j)]]; 4 edges/thread, L2-resident gathers.
__global__ __launch_bounds__(256) void k_out(const int* __restrict__ e32,
                                             float* __restrict__ out) {
    const int T = 1024 * 256;                            // total threads; 4*T == EE
    int t = blockIdx.x * 256 + threadIdx.x;
    int i0 = g_i0;
    int is64 = g_is64;
    if (t < NN) out[EE + t] = 0.0f;                      // self-loop rows: s[i]-s[i] == 0

    int r[4], c[4];
    #pragma unroll
    for (int i = 0; i < 4; i++) {
        int j = t + i * T;
        int m = j + i0; if (m >= EE) m -= EE;
        if (is64) { int4 v = __ldg(&((const int4*)e32)[m]); r[i] = v.x; c[i] = v.z; }
        else      { int2 v = __ldg(&((const int2*)e32)[m]); r[i] = v.x; c[i] = v.y; }
    }
    float o[4];
    #pragma unroll
    for (int i = 0; i < 4; i++) o[i] = __ldg(&g_sP[r[i]]) - __ldg(&g_sP[c[i]]);
    #pragma unroll
    for (int i = 0; i < 4; i++) out[t + i * T] = o[i];
}

extern "C" void kernel_launch(void* const* d_in, const int* in_sizes, int n_in,
                              void* d_out, int out_size) {
    const float* x  = (const float*)d_in[0];   // (N, 128) f32
    const int*   ei = (const int*)d_in[1];     // (E, 2) int32 or int64 (runtime-detected)
    const float* ed = (const float*)d_in[2];   // (E,) f32
    const float* w  = (const float*)d_in[3];   // (1, 128, 64) f32
    // d_in[4] = attention: provably unused (softmax of identical logits collapses)
    float* out = (float*)d_out;                // (E+N) f32

    k_main<<<GRID, 256>>>(x, w, ei);           // unified per-warp phases, 1 wave
    k_sP  <<<NN / 256, 256>>>(ei, ed);
    k_out <<<1024, 256>>>(ei, out);
}

// round 10
// speedup vs baseline: 1.3933x; 1.3933x over previous
#include <cuda_runtime.h>

#define NN   65536      // nodes
#define EE   1048576    // edges (NN*16)
#define CIN  128
#define COUT 64

#define TBLOCKS 480     // blocks doing the T (mat-vec) phase  (32 MB share)
#define BBLOCKS 112     // blocks doing the boundary phase     (8 MB share)
#define GRID    (TBLOCKS + BBLOCKS)   // 592 = 4 blocks/SM, one wave

// Scratch (no allocations allowed -> __device__ globals)
__device__ float g_T[NN];      // T[i] = x[i] . w_sum
__device__ int   g_start[NN];  // first edge index of node i's run (rows sorted)
__device__ int   g_end[NN];    // one-past-last edge index of node i's run
__device__ float g_sP[NN];     // s values at permuted positions 0..NN-1 (only ones used)
__device__ int   g_is64;       // 1 if edge_index stored as int64
__device__ int   g_i0;         // rotation offset from int32-overflow argsort (0 if int64)

// Pairwise merge: one shuffle merges two reduction trees.
__device__ __forceinline__ float merge_red(float a, float b, int dist, int lane) {
    bool hi = (lane & dist) != 0;
    float x = __shfl_xor_sync(0xffffffffu, hi ? a : b, dist);
    return (hi ? b : a) + x;
}

// K1: block-specialized (split matches the 4:1 byte ratio of the two streams).
//     Blocks [0,TBLOCKS): T[i]=x[i].wsum, 8 nodes/warp-iter (8 LDG.128 in flight,
//     7-shuffle merge reduction). Blocks [TBLOCKS,GRID): run-boundary stores over
//     sorted rows, batch-4 int4 loads. Block TBLOCKS also computes rotation i0.
__global__ __launch_bounds__(256, 4) void k_main(const float* __restrict__ x,
                                                 const float* __restrict__ w,
                                                 const int* __restrict__ e32) {
    __shared__ __align__(16) float s_ws[CIN];
    __shared__ int s_is64;
    int t = threadIdx.x, lane = t & 31, wrp = t >> 5;
    bool is_T = blockIdx.x < TBLOCKS;

    // dtype detect (all blocks): int64 => all odd int32 words are zero high-words
    if (wrp == 0) {
        int v = (lane < 16) ? e32[2 * lane + 1] : 0;
        unsigned b = __ballot_sync(0xffffffffu, v != 0);
        if (lane == 0) s_is64 = (b == 0) ? 1 : 0;
    }
    // wsum (T blocks only): wsum[c] = sum_o W[c][o], coalesced warp reductions
    if (is_T) {
        for (int c = wrp; c < CIN; c += 8) {
            float a = w[c * COUT + lane] + w[c * COUT + 32 + lane];
            #pragma unroll
            for (int o = 16; o; o >>= 1) a += __shfl_xor_sync(0xffffffffu, a, o);
            if (lane == 0) s_ws[c] = a;
        }
    }
    __syncthreads();
    int is64 = s_is64;

    // first boundary block, warp 7: 32-ary search for first row >= 32768
    if (blockIdx.x == TBLOCKS && wrp == 7) {
        int i0 = 0;
        if (!is64) {
            int lo = 0, hi = EE;
            while (hi - lo > 64) {
                long long len = hi - lo;
                int q = lo + (int)((len * (lane + 1)) / 33);
                int val = e32[(size_t)q * 2];
                unsigned b = __ballot_sync(0xffffffffu, val >= 32768);
                if (b == 0) {
                    lo = lo + (int)((len * 32) / 33);
                } else {
                    int k = __ffs(b) - 1;
                    int nhi = lo + (int)((len * (k + 1)) / 33);
                    int nlo = (k == 0) ? lo : (lo + (int)((len * (long long)k) / 33));
                    lo = nlo; hi = nhi;
                }
            }
            int p1 = lo + lane, p2 = lo + 32 + lane;
            int c1 = (p1 < hi && e32[(size_t)p1 * 2] < 32768) ? 1 : 0;
            int c2 = (p2 < hi && e32[(size_t)p2 * 2] < 32768) ? 1 : 0;
            unsigned b1 = __ballot_sync(0xffffffffu, c1);
            unsigned b2 = __ballot_sync(0xffffffffu, c2);
            i0 = lo + __popc(b1) + __popc(b2);
        }
        if (lane == 0) { g_is64 = is64; g_i0 = i0; }
    }

    if (is_T) {
        // ---- T phase: 8 consecutive nodes per warp-iter, MLP=8 ----
        const int nwarps = TBLOCKS * 8;                  // 3840
        float4 wv = ((const float4*)s_ws)[lane];
        for (int base = (blockIdx.x * 8 + wrp) * 8; base < NN; base += nwarps * 8) {
            float s[8];
            #pragma unroll
            for (int i = 0; i < 8; i++) {
                float4 xv = ((const float4*)(x + (size_t)(base + i) * CIN))[lane];
                s[i] = xv.x * wv.x + xv.y * wv.y + xv.z * wv.z + xv.w * wv.w;
            }
            // merge tree: 8 -> 4 -> 2 -> 1 values (7 shuffles), then 2-stage tail
            float m0 = merge_red(s[0], s[1], 16, lane);
            float m1 = merge_red(s[2], s[3], 16, lane);
            float m2 = merge_red(s[4], s[5], 16, lane);
            float m3 = merge_red(s[6], s[7], 16, lane);
            float n0 = merge_red(m0, m1, 8, lane);
            float n1 = merge_red(m2, m3, 8, lane);
            float p  = merge_red(n0, n1, 4, lane);
            p += __shfl_xor_sync(0xffffffffu, p, 2);
            p += __shfl_xor_sync(0xffffffffu, p, 1);
            // node offset encoded by lane bits {16,8,4}
            if ((lane & 3) == 0) {
                int off = ((lane >> 4) & 1) + ((lane >> 3) & 1) * 2 + ((lane >> 2) & 1) * 4;
                g_T[base + off] = p;
            }
        }
    } else {
        // ---- boundary phase: batch-4 strided int4 loads (MLP ~8 incl. peeks) ----
        const int S = BBLOCKS * 256;                     // 28672 threads
        int bt = (blockIdx.x - TBLOCKS) * 256 + t;
        const int4* p4 = (const int4*)e32;
        if (!is64) {
            const int U = EE / 2;                        // 524288 int4 units
            for (int g0 = bt; g0 < U; g0 += 4 * S) {
                int4 v[4]; int rn[4]; int gi[4]; int nv = 0;
                #pragma unroll
                for (int i = 0; i < 4; i++) {
                    int g = g0 + i * S;
                    if (g < U) {
                        gi[nv] = g;
                        v[nv] = p4[g];
                        size_t pk = (g < U - 1) ? (size_t)(2 * g + 2) * 2 : 0;
                        rn[nv] = __ldg(&e32[pk]);
                        nv++;
                    }
                }
                #pragma unroll
                for (int i = 0; i < 4; i++) {
                    if (i < nv) {
                        int g = gi[i];
                        int4 e = v[i];                   // edges 2g:(x,y) 2g+1:(z,w)
                        if (g == 0) g_start[e.x] = 0;
                        if (e.x != e.z) { g_end[e.x] = 2 * g + 1; g_start[e.z] = 2 * g + 1; }
                        if (g == U - 1) {
                            g_end[e.z] = EE;
                        } else if (e.z != rn[i]) {
                            g_end[e.z] = 2 * g + 2; g_start[rn[i]] = 2 * g + 2;
                        }
                    }
                }
            }
        } else {
            const int U = EE;                            // one edge per int4
            for (int g0 = bt; g0 < U; g0 += 4 * S) {
                int4 v[4]; int rn[4]; int gi[4]; int nv = 0;
                #pragma unroll
                for (int i = 0; i < 4; i++) {
                    int g = g0 + i * S;
                    if (g < U) {
                        gi[nv] = g;
                        v[nv] = p4[g];
                        size_t pk = (g < U - 1) ? (size_t)(g + 1) * 4 : 0;
                        rn[nv] = __ldg(&e32[pk]);
                        nv++;
                    }
                }
                #pragma unroll
                for (int i = 0; i < 4; i++) {
                    if (i < nv) {
                        int g = gi[i];
                        int4 e = v[i];                   // edge g: row=x, col=z
                        if (g == 0) g_start[e.x] = 0;
                        if (g == U - 1) {
                            g_end[e.x] = EE;
                        } else if (e.x != rn[i]) {
                            g_end[e.x] = g + 1; g_start[rn[i]] = g + 1;
                        }
                    }
                }
            }
        }
    }
}

// K2: sP[j] = 2*T[r]/(cnt[r]+1+1e-16)/ed[m], only for the NN positions ever gathered.
__global__ __launch_bounds__(256) void k_sP(const int* __restrict__ e32,
                                            const float* __restrict__ ed) {
    int j = blockIdx.x * 256 + threadIdx.x;              // j < NN
    int m = j + g_i0; if (m >= EE) m -= EE;
    int stride = g_is64 ? 4 : 2;
    int r = __ldg(&e32[(size_t)m * stride]);
    int cnt = g_end[r] - g_start[r];                     // out-degree (excl. self loop)
    float coef = 2.0f * g_T[r] / ((float)(cnt + 1) + 1e-16f);
    g_sP[j] = coef / ed[m];
}

// K3: out[j] = sP[row[rot(j)]] - sP[col[rot(j)]]; 4 edges/thread, L2-resident gathers.
__global__ __launch_bounds__(256) void k_out(const int* __restrict__ e32,
                                             float* __restrict__ out) {
    const int T = 1024 * 256;                            // total threads; 4*T == EE
    int t = blockIdx.x * 256 + threadIdx.x;
    int i0 = g_i0;
    int is64 = g_is64;
    if (t < NN) out[EE + t] = 0.0f;                      // self-loop rows: s[i]-s[i] == 0

    int r[4], c[4];
    #pragma unroll
    for (int i = 0; i < 4; i++) {
        int j = t + i * T;
        int m = j + i0; if (m >= EE) m -= EE;
        if (is64) { int4 v = __ldg(&((const int4*)e32)[m]); r[i] = v.x; c[i] = v.z; }
        else      { int2 v = __ldg(&((const int2*)e32)[m]); r[i] = v.x; c[i] = v.y; }
    }
    float o[4];
    #pragma unroll
    for (int i = 0; i < 4; i++) o[i] = __ldg(&g_sP[r[i]]) - __ldg(&g_sP[c[i]]);
    #pragma unroll
    for (int i = 0; i < 4; i++) out[t + i * T] = o[i];
}

extern "C" void kernel_launch(void* const* d_in, const int* in_sizes, int n_in,
                              void* d_out, int out_size) {
    const float* x  = (const float*)d_in[0];   // (N, 128) f32
    const int*   ei = (const int*)d_in[1];     // (E, 2) int32 or int64 (runtime-detected)
    const float* ed = (const float*)d_in[2];   // (E,) f32
    const float* w  = (const float*)d_in[3];   // (1, 128, 64) f32
    // d_in[4] = attention: provably unused (softmax of identical logits collapses)
    float* out = (float*)d_out;                // (E+N) f32

    k_main<<<GRID, 256>>>(x, w, ei);           // 480 T-blocks : 112 boundary-blocks (4:1)
    k_sP  <<<NN / 256, 256>>>(ei, ed);
    k_out <<<1024, 256>>>(ei, out);
}